// round 12
// baseline (speedup 1.0000x reference)
#include <cuda_runtime.h>

// Problem constants (from reference): B=128, S=256, D=1024, BETA=1.0
#define BB 128
#define SS 256
#define DD 1024
#define BETA_F 1.0f

#define NSM 148
#define BLOCKS_PER_SM 3
#define WARPS 4                        // warps per block (128 threads)
#define NBLOCKS (NSM * BLOCKS_PER_SM)  // 444 — one exact wave at occ=3
#define NTHREADS (WARPS * 32)          // 128
#define NWARPS_TOTAL (NBLOCKS * WARPS) // 1776
#define NROWS (SS - 2)                 // 254 interior rows per batch
#define TOTAL_Q (BB * NROWS)           // 32512 queries
#define REG_SHIFT 6                    // batch>>6 -> 2 row regions of 64 MB

__device__ float g_posv[TOTAL_Q];      // sum(xp^2)*inv per query
__device__ float g_negv[TOTAL_Q];      // sum(xn^2)*inv per query
__device__ unsigned g_ctr = 0;         // self-resetting via atomicInc wrap

// Consume buffer P (row xv), prefetch next row from 'npn' if 'hn'.
// Computes acc = sum (x - m)^2 with m = h + alpha*(t-h), two chains.
#define CONSUME_ROW(OUTARR, QIDX)                                             \
    do {                                                                      \
        float acc0 = 0.0f, acc1 = 0.0f;                                       \
        _Pragma("unroll")                                                     \
        for (int j = 0; j < 8; j++) {                                         \
            const float4 xv = P[j];                                           \
            if (hn) P[j] = npn[lane + j * 32];                                \
            const float4 hv = h[j], tv = tl[j];                               \
            const float mx = fmaf(alpha, tv.x - hv.x, hv.x);                  \
            const float my = fmaf(alpha, tv.y - hv.y, hv.y);                  \
            const float mz = fmaf(alpha, tv.z - hv.z, hv.z);                  \
            const float mw = fmaf(alpha, tv.w - hv.w, hv.w);                  \
            const float dx = xv.x - mx, dy = xv.y - my;                       \
            const float dz = xv.z - mz, dw = xv.w - mw;                       \
            acc0 = fmaf(dx, dx, acc0); acc1 = fmaf(dy, dy, acc1);             \
            acc0 = fmaf(dz, dz, acc0); acc1 = fmaf(dw, dw, acc1);             \
        }                                                                     \
        float acc = acc0 + acc1;                                              \
        _Pragma("unroll")                                                     \
        for (int off = 16; off; off >>= 1)                                    \
            acc += __shfl_xor_sync(0xffffffffu, acc, off);                    \
        if (lane == 0) OUTARR[QIDX] = acc * inv;                              \
    } while (0)

__global__ __launch_bounds__(NTHREADS, BLOCKS_PER_SM)
void bridge_loss_phased(const float* __restrict__ bridges,
                        const int*   __restrict__ b_inx,
                        const int*   __restrict__ neg_i,
                        const int*   __restrict__ neg_j,
                        float*       __restrict__ out)
{
    const int warp = threadIdx.x >> 5;
    const int lane = threadIdx.x & 31;
    const int gw   = blockIdx.x * WARPS + warp;   // 0..1775

    // balanced contiguous chunk of the flattened query space
    int q0 = (int)(((long long)gw       * TOTAL_Q) / NWARPS_TOTAL);
    int q1 = (int)(((long long)(gw + 1) * TOTAL_Q) / NWARPS_TOTAL);

    while (q0 < q1) {
        const int b  = q0 / NROWS;
        const int r0 = q0 - b * NROWS;
        const int r1 = min(q1 - b * NROWS, NROWS);
        q0 = b * NROWS + r1;

        const float4* base = (const float4*)(bridges + (size_t)b * SS * DD);
        const float4* tp4  = base + (size_t)(SS - 1) * (DD / 4);

        // own-batch head/tail, register-resident (mandatory per R3/R8)
        float4 h[8], tl[8];
#pragma unroll
        for (int j = 0; j < 8; j++) {
            h[j]  = base[lane + j * 32];
            tl[j] = tp4 [lane + j * 32];
        }

        const float th = (float)b_inx[b * SS];
        const float tt = (float)b_inx[b * SS + SS - 1];
        const float inv_den = 1.0f / (tt - th);
        const int gb = b >> REG_SHIFT;            // region of this batch's rows

        float4 P[8];

        for (int g = 0; g < 2; g++) {
            // ---- pos pass (only in the region where this batch lives) ----
            if (gb == g) {
                {
                    const float4* pp =
                        (const float4*)(bridges + ((size_t)b * SS + r0 + 1) * DD);
#pragma unroll
                    for (int j = 0; j < 8; j++) P[j] = pp[lane + j * 32];
                }
                for (int r = r0; r < r1; r++) {
                    const float tpv   = (float)b_inx[b * SS + r + 1];
                    const float alpha = (tpv - th) * inv_den;
                    const float sigma = alpha * (tt - tpv);
                    const float inv   = 1.0f / (2.0f * sigma * sigma);
                    const bool hn = (r + 1) < r1;
                    const float4* npn = hn
                        ? (const float4*)(bridges + ((size_t)b * SS + r + 2) * DD)
                        : base;
                    CONSUME_ROW(g_posv, b * NROWS + r);
                }
            }

            // ---- neg pass for region g (gathers confined to hot region) ----
            int rA = r0;
            while (rA < r1 && (neg_i[b * NROWS + rA] >> REG_SHIFT) != g) rA++;
            if (rA < r1) {
                {
                    const int ni = neg_i[b * NROWS + rA];
                    const int nj = neg_j[b * NROWS + rA];
                    const float4* np =
                        (const float4*)(bridges + ((size_t)ni * SS + nj) * DD);
#pragma unroll
                    for (int j = 0; j < 8; j++) P[j] = np[lane + j * 32];
                }
                while (rA < r1) {
                    int rB = rA + 1;
                    while (rB < r1 && (neg_i[b * NROWS + rB] >> REG_SHIFT) != g) rB++;
                    const bool hn = rB < r1;
                    const float4* npn = base;
                    if (hn) {
                        const int ni = neg_i[b * NROWS + rB];
                        const int nj = neg_j[b * NROWS + rB];
                        npn = (const float4*)(bridges + ((size_t)ni * SS + nj) * DD);
                    }
                    const float tpv   = (float)b_inx[b * SS + rA + 1];
                    const float alpha = (tpv - th) * inv_den;
                    const float sigma = alpha * (tt - tpv);
                    const float inv   = 1.0f / (2.0f * sigma * sigma);
                    CONSUME_ROW(g_negv, b * NROWS + rA);
                    rA = rB;
                }
            }
        }
    }

    // ---- completion counter + last-block deterministic combine ----
    __shared__ bool amLast;
    __syncthreads();
    __threadfence();
    if (threadIdx.x == 0) {
        unsigned old = atomicInc(&g_ctr, NBLOCKS - 1);   // wraps -> replay safe
        amLast = (old == NBLOCKS - 1);
    }
    __syncthreads();

    if (amLast) {
        float t = 0.0f;
#pragma unroll 4
        for (int i = threadIdx.x; i < TOTAL_Q; i += NTHREADS) {
            const float cur = g_negv[i] - g_posv[i] + BETA_F;
            t += fmaxf(cur, 0.0f);
        }
        __shared__ float fin[NTHREADS];
        fin[threadIdx.x] = t;
        __syncthreads();
#pragma unroll
        for (int st = NTHREADS / 2; st > 0; st >>= 1) {
            if ((int)threadIdx.x < st) fin[threadIdx.x] += fin[threadIdx.x + st];
            __syncthreads();
        }
        if (threadIdx.x == 0) out[0] = fin[0] / (float)BB;
    }
}

extern "C" void kernel_launch(void* const* d_in, const int* in_sizes, int n_in,
                              void* d_out, int out_size)
{
    const float* bridges = (const float*)d_in[0];
    const int*   b_inx   = (const int*)  d_in[1];
    const int*   neg_i   = (const int*)  d_in[2];
    const int*   neg_j   = (const int*)  d_in[3];

    bridge_loss_phased<<<NBLOCKS, NTHREADS>>>(bridges, b_inx, neg_i, neg_j,
                                              (float*)d_out);
}

// round 13
// speedup vs baseline: 2.0853x; 2.0853x over previous
#include <cuda_runtime.h>

// Problem constants (from reference): B=128, S=256, D=1024, BETA=1.0
#define BB 128
#define SS 256
#define DD 1024
#define BETA_F 1.0f

#define NSM 148
#define OCC_MAIN 5
#define WARPS 4                          // warps per block (128 threads)
#define NTHREADS (WARPS * 32)            // 128
#define NBLOCKS_MAIN (NSM * OCC_MAIN)    // 740 — one exact wave at occ=5
#define NWARPS_TOTAL (NBLOCKS_MAIN * WARPS) // 2960
#define NROWS (SS - 2)                   // 254 interior rows per batch
#define TOTAL_Q (BB * NROWS)             // 32512 queries
#define TOTAL_HQ (2 * TOTAL_Q)           // 65024 query-halves

#define CB_BLOCKS (TOTAL_Q / NTHREADS)   // 254 (exact)

// Per-query-half alpha-free partials: A = sum(n^2-p^2), Bh = sum h*(n-p),
// Bt = sum t*(n-p), each over 512 dims.
__device__ float g_A [2][TOTAL_Q];
__device__ float g_Bh[2][TOTAL_Q];
__device__ float g_Bt[2][TOTAL_Q];
__device__ float g_partials[CB_BLOCKS];
__device__ unsigned g_ctr = 0;           // self-resetting via atomicInc wrap

// ---------------- main kernel: half-row streaming ----------------

__device__ __forceinline__ void process_segment(
    const float* __restrict__ bridges,
    const int*   __restrict__ neg_i,
    const int*   __restrict__ neg_j,
    int half, int b, int r0, int r1, int lane)
{
    const float4* base = (const float4*)(bridges + (size_t)b * SS * DD);
    const int hoff = half * 128;                  // float4 offset of this half

    // own-batch head/tail halves, register-resident
    float4 h[4], tl[4];
    {
        const float4* hp  = base + hoff;
        const float4* tp4 = base + (size_t)(SS - 1) * (DD / 4) + hoff;
#pragma unroll
        for (int j = 0; j < 4; j++) {
            h[j]  = hp [lane + j * 32];
            tl[j] = tp4[lane + j * 32];
        }
    }

    float4 P[4], N[4];

    // prologue: row r0 halves in flight (8 LDG.128)
    {
        const float4* pp =
            (const float4*)(bridges + ((size_t)b * SS + r0 + 1) * DD) + hoff;
        const int ni = neg_i[b * NROWS + r0];
        const int nj = neg_j[b * NROWS + r0];
        const float4* np =
            (const float4*)(bridges + ((size_t)ni * SS + nj) * DD) + hoff;
#pragma unroll
        for (int j = 0; j < 4; j++) {
            P[j] = pp[lane + j * 32];
            N[j] = np[lane + j * 32];
        }
    }

    int r = r0;
    while (r < r1) {
        const int rn = r + 1;
        const bool hn = rn < r1;
        const float4* ppn = base;                 // safe dummy
        const float4* npn = base;
        if (hn) {
            ppn = (const float4*)(bridges + ((size_t)b * SS + rn + 1) * DD) + hoff;
            const int ni = neg_i[b * NROWS + rn];
            const int nj = neg_j[b * NROWS + rn];
            npn = (const float4*)(bridges + ((size_t)ni * SS + nj) * DD) + hoff;
        }

        float accA = 0.0f, accBh = 0.0f, accBt = 0.0f;
#pragma unroll
        for (int j = 0; j < 4; j++) {
            const float4 pv = P[j], nv = N[j];
            if (hn) {                             // prefetch next row, chunk j
                P[j] = ppn[lane + j * 32];
                N[j] = npn[lane + j * 32];
            }
            const float4 hv = h[j], tv = tl[j];
            const float dx = nv.x - pv.x, sx = nv.x + pv.x;
            const float dy = nv.y - pv.y, sy = nv.y + pv.y;
            const float dz = nv.z - pv.z, sz = nv.z + pv.z;
            const float dw = nv.w - pv.w, sw = nv.w + pv.w;
            accA  = fmaf(sx,   dx, accA);
            accBh = fmaf(hv.x, dx, accBh);
            accBt = fmaf(tv.x, dx, accBt);
            accA  = fmaf(sy,   dy, accA);
            accBh = fmaf(hv.y, dy, accBh);
            accBt = fmaf(tv.y, dy, accBt);
            accA  = fmaf(sz,   dz, accA);
            accBh = fmaf(hv.z, dz, accBh);
            accBt = fmaf(tv.z, dz, accBt);
            accA  = fmaf(sw,   dw, accA);
            accBh = fmaf(hv.w, dw, accBh);
            accBt = fmaf(tv.w, dw, accBt);
        }

#pragma unroll
        for (int off = 16; off; off >>= 1) {
            accA  += __shfl_xor_sync(0xffffffffu, accA,  off);
            accBh += __shfl_xor_sync(0xffffffffu, accBh, off);
            accBt += __shfl_xor_sync(0xffffffffu, accBt, off);
        }

        if (lane == 0) {
            const int qi = b * NROWS + r;
            g_A [half][qi] = accA;
            g_Bh[half][qi] = accBh;
            g_Bt[half][qi] = accBt;
        }
        r = rn;
    }
}

__global__ __launch_bounds__(NTHREADS, OCC_MAIN)
void bridge_loss_half(const float* __restrict__ bridges,
                      const int*   __restrict__ neg_i,
                      const int*   __restrict__ neg_j)
{
    const int warp = threadIdx.x >> 5;
    const int lane = threadIdx.x & 31;
    const int gw   = blockIdx.x * WARPS + warp;   // 0..2959

    // balanced contiguous chunk of the flattened (half, b, r) space (half-major)
    int s = (int)(((long long)gw       * TOTAL_HQ) / NWARPS_TOTAL);
    int e = (int)(((long long)(gw + 1) * TOTAL_HQ) / NWARPS_TOTAL);

    while (s < e) {
        const int half = s / TOTAL_Q;
        const int w    = s - half * TOTAL_Q;
        const int b    = w / NROWS;
        const int r0   = w - b * NROWS;
        const int lim  = min(e - half * TOTAL_Q, (b + 1) * NROWS);
        const int r1   = lim - b * NROWS;
        process_segment(bridges, neg_i, neg_j, half, b, r0, r1, lane);
        s = half * TOTAL_Q + b * NROWS + r1;
    }
}

// ---------------- combine kernel: halves -> loss ----------------

__global__ __launch_bounds__(NTHREADS)
void bridge_loss_combine(const int* __restrict__ b_inx,
                         float*     __restrict__ out)
{
    const int q = blockIdx.x * NTHREADS + threadIdx.x;   // 254*128 = 32512 exact
    const int b = q / NROWS;
    const int r = q - b * NROWS;

    const float th = (float)b_inx[b * SS];
    const float tt = (float)b_inx[b * SS + SS - 1];
    const float tp = (float)b_inx[b * SS + r + 1];
    const float alpha = (tp - th) / (tt - th);
    const float sigma = alpha * (tt - tp);
    const float inv   = 1.0f / (2.0f * sigma * sigma);

    const float A  = g_A [0][q] + g_A [1][q];
    const float Bh = g_Bh[0][q] + g_Bh[1][q];
    const float Bt = g_Bt[0][q] + g_Bt[1][q];

    const float mdot = fmaf(alpha, Bt, (1.0f - alpha) * Bh);
    const float diff = fmaf(-2.0f, mdot, A);
    const float cur  = fmaf(diff, inv, BETA_F);
    float v = cur > 0.0f ? cur : 0.0f;

    __shared__ float sm[NTHREADS];
    __shared__ bool  amLast;
    sm[threadIdx.x] = v;
    __syncthreads();
#pragma unroll
    for (int st = NTHREADS / 2; st > 0; st >>= 1) {
        if ((int)threadIdx.x < st) sm[threadIdx.x] += sm[threadIdx.x + st];
        __syncthreads();
    }
    if (threadIdx.x == 0) {
        g_partials[blockIdx.x] = sm[0];
        __threadfence();
        unsigned old = atomicInc(&g_ctr, CB_BLOCKS - 1);  // wraps -> replay safe
        amLast = (old == CB_BLOCKS - 1);
    }
    __syncthreads();

    if (amLast) {
        __shared__ float fin[NTHREADS];
        float t = g_partials[threadIdx.x];
        if (threadIdx.x + NTHREADS < CB_BLOCKS)
            t += g_partials[threadIdx.x + NTHREADS];
        fin[threadIdx.x] = t;
        __syncthreads();
#pragma unroll
        for (int st = NTHREADS / 2; st > 0; st >>= 1) {
            if ((int)threadIdx.x < st) fin[threadIdx.x] += fin[threadIdx.x + st];
            __syncthreads();
        }
        if (threadIdx.x == 0) out[0] = fin[0] / (float)BB;
    }
}

extern "C" void kernel_launch(void* const* d_in, const int* in_sizes, int n_in,
                              void* d_out, int out_size)
{
    const float* bridges = (const float*)d_in[0];
    const int*   b_inx   = (const int*)  d_in[1];
    const int*   neg_i   = (const int*)  d_in[2];
    const int*   neg_j   = (const int*)  d_in[3];

    bridge_loss_half<<<NBLOCKS_MAIN, NTHREADS>>>(bridges, neg_i, neg_j);
    bridge_loss_combine<<<CB_BLOCKS, NTHREADS>>>(b_inx, (float*)d_out);
}

// round 14
// speedup vs baseline: 2.3123x; 1.1089x over previous
#include <cuda_runtime.h>

// Problem constants (from reference): B=128, S=256, D=1024, BETA=1.0
#define BB 128
#define SS 256
#define DD 1024
#define BETA_F 1.0f

#define NSM 148
#define OCC_MAIN 5
#define WARPS 4                          // warps per block (128 threads)
#define NTHREADS (WARPS * 32)            // 128
#define NBLOCKS (NSM * OCC_MAIN)         // 740 — one exact wave at occ=5
#define NPAIRS (NBLOCKS * 2)             // 1480 warp-pairs
#define NROWS (SS - 2)                   // 254 interior rows per batch
#define TOTAL_Q (BB * NROWS)             // 32512 queries
#define MAXQ 24                          // max queries per pair (22 actual)

__device__ float g_partials[NBLOCKS];
__device__ unsigned g_ctr = 0;           // self-resetting via atomicInc wrap

// Stream rows [r0, r1) of batch b, D-half 'half'; store per-row (A,Bh,Bt)
// into smem slots (q - pair_start). Dist-1 pipelined prefetch (R13 structure).
__device__ __forceinline__ void process_segment(
    const float* __restrict__ bridges,
    const int*   __restrict__ neg_i,
    const int*   __restrict__ neg_j,
    float (*sm)[2][3],                  // [slot][half][A,Bh,Bt]
    int pair_start, int half, int b, int r0, int r1, int lane)
{
    const float4* base = (const float4*)(bridges + (size_t)b * SS * DD);
    const int hoff = half * 128;                  // float4 offset of this half

    // own-batch head/tail halves, register-resident
    float4 h[4], tl[4];
    {
        const float4* hp  = base + hoff;
        const float4* tp4 = base + (size_t)(SS - 1) * (DD / 4) + hoff;
#pragma unroll
        for (int j = 0; j < 4; j++) {
            h[j]  = hp [lane + j * 32];
            tl[j] = tp4[lane + j * 32];
        }
    }

    float4 P[4], N[4];

    // prologue: row r0 halves in flight (8 LDG.128)
    {
        const float4* pp =
            (const float4*)(bridges + ((size_t)b * SS + r0 + 1) * DD) + hoff;
        const int ni = neg_i[b * NROWS + r0];
        const int nj = neg_j[b * NROWS + r0];
        const float4* np =
            (const float4*)(bridges + ((size_t)ni * SS + nj) * DD) + hoff;
#pragma unroll
        for (int j = 0; j < 4; j++) {
            P[j] = pp[lane + j * 32];
            N[j] = np[lane + j * 32];
        }
    }

    int r = r0;
    while (r < r1) {
        const int rn = r + 1;
        const bool hn = rn < r1;
        const float4* ppn = base;                 // safe dummy
        const float4* npn = base;
        if (hn) {
            ppn = (const float4*)(bridges + ((size_t)b * SS + rn + 1) * DD) + hoff;
            const int ni = neg_i[b * NROWS + rn];
            const int nj = neg_j[b * NROWS + rn];
            npn = (const float4*)(bridges + ((size_t)ni * SS + nj) * DD) + hoff;
        }

        // A = sum (n^2 - p^2); Bh = sum h*(n-p); Bt = sum t*(n-p)
        float accA = 0.0f, accBh = 0.0f, accBt = 0.0f;
#pragma unroll
        for (int j = 0; j < 4; j++) {
            const float4 pv = P[j], nv = N[j];
            if (hn) {                             // prefetch next row, chunk j
                P[j] = ppn[lane + j * 32];
                N[j] = npn[lane + j * 32];
            }
            const float4 hv = h[j], tv = tl[j];
            const float dx = nv.x - pv.x, sx = nv.x + pv.x;
            const float dy = nv.y - pv.y, sy = nv.y + pv.y;
            const float dz = nv.z - pv.z, sz = nv.z + pv.z;
            const float dw = nv.w - pv.w, sw = nv.w + pv.w;
            accA  = fmaf(sx,   dx, accA);
            accBh = fmaf(hv.x, dx, accBh);
            accBt = fmaf(tv.x, dx, accBt);
            accA  = fmaf(sy,   dy, accA);
            accBh = fmaf(hv.y, dy, accBh);
            accBt = fmaf(tv.y, dy, accBt);
            accA  = fmaf(sz,   dz, accA);
            accBh = fmaf(hv.z, dz, accBh);
            accBt = fmaf(tv.z, dz, accBt);
            accA  = fmaf(sw,   dw, accA);
            accBh = fmaf(hv.w, dw, accBh);
            accBt = fmaf(tv.w, dw, accBt);
        }

#pragma unroll
        for (int off = 16; off; off >>= 1) {
            accA  += __shfl_xor_sync(0xffffffffu, accA,  off);
            accBh += __shfl_xor_sync(0xffffffffu, accBh, off);
            accBt += __shfl_xor_sync(0xffffffffu, accBt, off);
        }

        if (lane == 0) {
            const int slot = b * NROWS + r - pair_start;
            sm[slot][half][0] = accA;
            sm[slot][half][1] = accBh;
            sm[slot][half][2] = accBt;
        }
        r = rn;
    }
}

__global__ __launch_bounds__(NTHREADS, OCC_MAIN)
void bridge_loss_paired(const float* __restrict__ bridges,
                        const int*   __restrict__ b_inx,
                        const int*   __restrict__ neg_i,
                        const int*   __restrict__ neg_j,
                        float*       __restrict__ out)
{
    const int warp = threadIdx.x >> 5;
    const int lane = threadIdx.x & 31;
    const int pairLocal = warp >> 1;              // 0..1
    const int half      = warp & 1;               // D-half owned by this warp
    const int gp = blockIdx.x * 2 + pairLocal;    // 0..1479

    __shared__ float sm_part[2][MAXQ][2][3];      // [pair][slot][half][A,Bh,Bt]
    __shared__ float pair_loss[2];
    __shared__ bool  amLast;

    // balanced contiguous query chunk for this pair (both halves walk it)
    const int pair_start = (int)(((long long)gp       * TOTAL_Q) / NPAIRS);
    const int pair_end   = (int)(((long long)(gp + 1) * TOTAL_Q) / NPAIRS);

    int s = pair_start;
    while (s < pair_end) {
        const int b  = s / NROWS;
        const int r0 = s - b * NROWS;
        const int r1 = min(pair_end - b * NROWS, NROWS);
        process_segment(bridges, neg_i, neg_j, sm_part[pairLocal],
                        pair_start, half, b, r0, r1, lane);
        s = b * NROWS + r1;
    }

    __syncthreads();

    // combine: even warp of each pair, one lane per query
    if (half == 0) {
        const int len = pair_end - pair_start;    // <= 22
        float v = 0.0f;
        if (lane < len) {
            const int q = pair_start + lane;
            const int b = q / NROWS;
            const int r = q - b * NROWS;
            const float th = (float)b_inx[b * SS];
            const float tt = (float)b_inx[b * SS + SS - 1];
            const float tp = (float)b_inx[b * SS + r + 1];
            const float alpha = (tp - th) / (tt - th);
            const float sigma = alpha * (tt - tp);
            const float inv   = 1.0f / (2.0f * sigma * sigma);

            const float A  = sm_part[pairLocal][lane][0][0] + sm_part[pairLocal][lane][1][0];
            const float Bh = sm_part[pairLocal][lane][0][1] + sm_part[pairLocal][lane][1][1];
            const float Bt = sm_part[pairLocal][lane][0][2] + sm_part[pairLocal][lane][1][2];

            const float mdot = fmaf(alpha, Bt, (1.0f - alpha) * Bh);
            const float diff = fmaf(-2.0f, mdot, A);
            const float cur  = fmaf(diff, inv, BETA_F);
            v = cur > 0.0f ? cur : 0.0f;
        }
#pragma unroll
        for (int off = 16; off; off >>= 1)
            v += __shfl_xor_sync(0xffffffffu, v, off);
        if (lane == 0) pair_loss[pairLocal] = v;
    }
    __syncthreads();

    if (threadIdx.x == 0) {
        g_partials[blockIdx.x] = pair_loss[0] + pair_loss[1];
        __threadfence();
        unsigned old = atomicInc(&g_ctr, NBLOCKS - 1);   // wraps -> replay safe
        amLast = (old == NBLOCKS - 1);
    }
    __syncthreads();

    if (amLast) {
        __shared__ float fin[NTHREADS];
        float t = 0.0f;
#pragma unroll
        for (int k = 0; k < (NBLOCKS + NTHREADS - 1) / NTHREADS; k++) {
            const int idx = threadIdx.x + k * NTHREADS;
            if (idx < NBLOCKS) t += g_partials[idx];
        }
        fin[threadIdx.x] = t;
        __syncthreads();
#pragma unroll
        for (int st = NTHREADS / 2; st > 0; st >>= 1) {
            if ((int)threadIdx.x < st) fin[threadIdx.x] += fin[threadIdx.x + st];
            __syncthreads();
        }
        if (threadIdx.x == 0) out[0] = fin[0] / (float)BB;
    }
}

extern "C" void kernel_launch(void* const* d_in, const int* in_sizes, int n_in,
                              void* d_out, int out_size)
{
    const float* bridges = (const float*)d_in[0];
    const int*   b_inx   = (const int*)  d_in[1];
    const int*   neg_i   = (const int*)  d_in[2];
    const int*   neg_j   = (const int*)  d_in[3];

    bridge_loss_paired<<<NBLOCKS, NTHREADS>>>(bridges, b_inx, neg_i, neg_j,
                                              (float*)d_out);
}